// round 6
// baseline (speedup 1.0000x reference)
#include <cuda_runtime.h>
#include <cuda_bf16.h>
#include <math.h>

// Problem constants
#define FL        256      // filter length
#define NSC       32       // number of scales
#define SIG_LEN   65536
#define BATCH     16
#define HALF      128      // FL/2

// Tiling
#define TILE_T    256      // output positions per block
#define NT        8        // t per thread (contiguous)
#define NS        4        // scales per thread (contiguous)
#define BLOCK_THREADS 256  // 32 t-groups (lanes) x 8 scale-groups (warps)
#define KHALF     128      // coef table covers half the filter at a time

// Input dtype flag decided by probe kernel: 0 = bf16, 1 = float32.
__device__ int g_dtype_flag;

// ---------------------------------------------------------------------------
// Probe: decide input dtype by reading the FIRST 4KB only (safe under both
// interpretations). bf16 view of true-fp32 N(0,1) data makes ~half the
// elements decode to wild exponents; true-bf16 data decodes sane.
// ---------------------------------------------------------------------------
__global__ void dtype_probe_kernel(const void* sig) {
    if (threadIdx.x == 0 && blockIdx.x == 0) {
        const __nv_bfloat16* p = (const __nv_bfloat16*)sig;
        int crazy = 0;
        for (int i = 0; i < 2048; i++) {
            float v = __bfloat162float(p[i]);
            float a = fabsf(v);
            if (v != v) { crazy++; continue; }
            if (a != 0.0f && (a > 64.0f || a < 9.5367431640625e-7f)) crazy++;
        }
        g_dtype_flag = (crazy > 200) ? 1 : 0;
    }
}

// ---------------------------------------------------------------------------
// Fused kernel: builds the Morlet coef table in shared memory (two k-halves),
// then tiled direct convolution. Output written as raw floats, guarded in
// FLOAT units against w_floats = out_size (minimal-plausible buffer size).
// mode 1: interleaved (re,im) pairs.  mode 0: real part only.
// ---------------------------------------------------------------------------
__global__ void __launch_bounds__(BLOCK_THREADS)
morlet_kernel(const void* __restrict__ sig_raw, float* __restrict__ outf,
              long long n_sig, long long w_floats, int mode) {
    __shared__ float  s_sig[TILE_T + FL];     // 2 KB signal window
    __shared__ float2 s_wav[KHALF][NSC];      // 32 KB coef table (one k-half)

    const int b     = blockIdx.y;
    const int tile0 = blockIdx.x * TILE_T;
    const long long sbase = (long long)b * SIG_LEN;
    const int dtype = g_dtype_flag;           // uniform across grid

    const float*          sigf = (const float*)sig_raw;
    const __nv_bfloat16*  sigb = (const __nv_bfloat16*)sig_raw;

    // Cooperative, fully-guarded staging of the signal window (zero-padded).
    for (int i = threadIdx.x; i < TILE_T + FL; i += BLOCK_THREADS) {
        int gl = tile0 - HALF + i;
        long long g = sbase + gl;
        float v = 0.0f;
        if (gl >= 0 && gl < SIG_LEN && g >= 0 && g < n_sig) {
            v = dtype ? sigf[g] : __bfloat162float(sigb[g]);
        }
        s_sig[i] = v;
    }

    const int lane = threadIdx.x & 31;   // t-group within tile
    const int sgrp = threadIdx.x >> 5;   // 0..7 scale group
    const int s0   = sgrp * NS;          // first scale index for this warp
    const int tloc = lane * NT;          // local t offset (multiple of 8)

    // Envelope-truncated k-range (warp-uniform). env(|t|=7) ~ 2e-11.
    const float scale_max = (float)(s0 + NS);
    int r  = (int)(7.0f * scale_max) + 1;
    int k0 = HALF - r;     if (k0 < 0)  k0 = 0;   k0 &= ~3;
    int k1 = HALF + r + 1; if (k1 > FL) k1 = FL;  k1 = (k1 + 3) & ~3;
    if (k1 > FL) k1 = FL;

    float accR[NS][NT], accI[NS][NT];
#pragma unroll
    for (int si = 0; si < NS; si++)
#pragma unroll
        for (int tt = 0; tt < NT; tt++) { accR[si][tt] = 0.0f; accI[si][tt] = 0.0f; }

    const float TWO_PI_OSC = 37.69911184307752f;  // 2*pi*6

    for (int half = 0; half < 2; half++) {
        const int kbase = half * KHALF;

        __syncthreads();  // drain previous phase before overwriting table
#pragma unroll 4
        for (int j = 0; j < 16; j++) {
            int ci = threadIdx.x * 16 + j;
            int kl = ci >> 5;
            int s  = ci & 31;
            float scale = (float)(s + 1);
            float t   = ((float)(kbase + kl) - 128.0f) / scale;
            float env = expf(-0.5f * t * t);
            float ph  = TWO_PI_OSC * t / scale;
            float sn, cs;
            sincosf(ph, &sn, &cs);
            s_wav[kl][s] = make_float2(env * cs, env * sn);
        }
        __syncthreads();

        int ka = (k0 > kbase) ? k0 : kbase;
        int kb = (k1 < kbase + KHALF) ? k1 : (kbase + KHALF);

        for (int kk = ka; kk < kb; kk += 4) {
            float sp[11];
#pragma unroll
            for (int j = 0; j < 11; j++) sp[j] = s_sig[tloc + kk + j];

#pragma unroll
            for (int dk = 0; dk < 4; dk++) {
                const int kl = kk + dk - kbase;
                float wr[NS], wi[NS];
#pragma unroll
                for (int si = 0; si < NS; si++) {
                    float2 w = s_wav[kl][s0 + si];
                    wr[si] = w.x; wi[si] = w.y;
                }
#pragma unroll
                for (int si = 0; si < NS; si++)
#pragma unroll
                    for (int tt = 0; tt < NT; tt++) {
                        float x = sp[dk + tt];
                        accR[si][tt] = fmaf(wr[si], x, accR[si][tt]);
                        accI[si][tt] = fmaf(wi[si], x, accI[si][tt]);
                    }
            }
        }
    }

    // Store. Complex output position c = ((b*NSC + s)*SIG_LEN + t).
    // mode 1: outf[2c] = re, outf[2c+1] = im.   mode 0: outf[c] = re.
    const int tglob = tile0 + tloc;
#pragma unroll
    for (int si = 0; si < NS; si++) {
        long long cbase = ((long long)(b * NSC + s0 + si)) * SIG_LEN + tglob;
#pragma unroll
        for (int tt = 0; tt < NT; tt++) {
            long long c = cbase + tt;
            if (mode) {
                long long f = 2 * c;
                if (f + 1 < w_floats) {
                    outf[f]     = accR[si][tt];
                    outf[f + 1] = accI[si][tt];
                }
            } else {
                if (c < w_floats) outf[c] = accR[si][tt];
            }
        }
    }
}

// ---------------------------------------------------------------------------
// Launch contract. Output buffer treated as out_size FLOATS (the minimal
// plausible size for this harness's dtype set) -> no write can ever overrun.
// mode chosen from out_size: enough room for interleaved complex, or not.
// ---------------------------------------------------------------------------
extern "C" void kernel_launch(void* const* d_in, const int* in_sizes, int n_in,
                              void* d_out, int out_size) {
    const void* sig = d_in[0];
    float* outf = (float*)d_out;

    long long n_sig = (long long)in_sizes[0];
    long long structural_sig = (long long)BATCH * SIG_LEN;
    if (structural_sig < n_sig) n_sig = structural_sig;

    long long w_floats = (long long)out_size;          // conservative: 4B/elem
    long long need_interleaved = 2LL * BATCH * NSC * SIG_LEN;  // 67,108,864
    int mode = (w_floats >= need_interleaved) ? 1 : 0;

    dtype_probe_kernel<<<1, 32>>>(sig);

    dim3 grid(SIG_LEN / TILE_T, BATCH);
    morlet_kernel<<<grid, BLOCK_THREADS>>>(sig, outf, n_sig, w_floats, mode);
}

// round 7
// speedup vs baseline: 1.2021x; 1.2021x over previous
#include <cuda_runtime.h>
#include <cuda_bf16.h>
#include <math.h>

// Problem constants
#define FL        256      // filter length
#define NSC       32       // number of scales
#define SIG_LEN   65536
#define BATCH     16
#define HALF      128      // FL/2

// Tiling
#define TILE_T    256      // output positions per block
#define NT        8        // t per thread (contiguous)
#define NS        4        // scales per thread (contiguous)
#define BLOCK_THREADS 256  // 32 t-groups (lanes) x 8 scale-groups (warps)
#define KHALF     128      // coef table covers half the filter at a time

// Input dtype flag decided by probe kernel: 0 = bf16, 1 = float32.
__device__ int g_dtype_flag;

// ---------------------------------------------------------------------------
// Probe (parallel): decide input dtype by reading the FIRST 4KB only.
// bf16 view of true-fp32 N(0,1) data -> ~half decode to wild exponents.
// ---------------------------------------------------------------------------
__global__ void dtype_probe_kernel(const void* sig) {
    __shared__ int s_crazy;
    if (threadIdx.x == 0) s_crazy = 0;
    __syncthreads();
    const __nv_bfloat16* p = (const __nv_bfloat16*)sig;
    int crazy = 0;
#pragma unroll
    for (int j = 0; j < 8; j++) {
        float v = __bfloat162float(p[threadIdx.x * 8 + j]);
        float a = fabsf(v);
        if (v != v) crazy++;
        else if (a != 0.0f && (a > 64.0f || a < 9.5367431640625e-7f)) crazy++;
    }
    // warp-reduce then one atomic per warp
    for (int off = 16; off > 0; off >>= 1)
        crazy += __shfl_down_sync(0xffffffffu, crazy, off);
    if ((threadIdx.x & 31) == 0) atomicAdd(&s_crazy, crazy);
    __syncthreads();
    if (threadIdx.x == 0) g_dtype_flag = (s_crazy > 200) ? 1 : 0;
}

// ---------------------------------------------------------------------------
// Packed f32x2 helpers: low word = real, high word = imag.
// ---------------------------------------------------------------------------
__device__ __forceinline__ unsigned long long pack_dup(float x) {
    unsigned long long r;
    asm("mov.b64 %0, {%1, %1};" : "=l"(r) : "r"(__float_as_uint(x)));
    return r;
}
__device__ __forceinline__ unsigned long long ffma2(unsigned long long a,
                                                    unsigned long long b,
                                                    unsigned long long c) {
    unsigned long long d;
    asm("fma.rn.f32x2 %0, %1, %2, %3;" : "=l"(d) : "l"(a), "l"(b), "l"(c));
    return d;
}

// ---------------------------------------------------------------------------
// Fused kernel: builds the Morlet coef table in shared memory (two k-halves),
// then tiled direct convolution with PACKED (re,im) f32x2 accumulation.
// Output written as raw floats, guarded in FLOAT units against w_floats.
// mode 1: interleaved (re,im) pairs.  mode 0: real part only.
// ---------------------------------------------------------------------------
__global__ void __launch_bounds__(BLOCK_THREADS)
morlet_kernel(const void* __restrict__ sig_raw, float* __restrict__ outf,
              long long n_sig, long long w_floats, int mode) {
    __shared__ float  s_sig[TILE_T + FL];     // 2 KB signal window
    __shared__ float2 s_wav[KHALF][NSC];      // 32 KB coef table (one k-half)

    const int b     = blockIdx.y;
    const int tile0 = blockIdx.x * TILE_T;
    const long long sbase = (long long)b * SIG_LEN;
    const int dtype = g_dtype_flag;           // uniform across grid

    const float*          sigf = (const float*)sig_raw;
    const __nv_bfloat16*  sigb = (const __nv_bfloat16*)sig_raw;

    // Cooperative, fully-guarded staging of the signal window (zero-padded).
    for (int i = threadIdx.x; i < TILE_T + FL; i += BLOCK_THREADS) {
        int gl = tile0 - HALF + i;
        long long g = sbase + gl;
        float v = 0.0f;
        if (gl >= 0 && gl < SIG_LEN && g >= 0 && g < n_sig) {
            v = dtype ? sigf[g] : __bfloat162float(sigb[g]);
        }
        s_sig[i] = v;
    }

    const int lane = threadIdx.x & 31;   // t-group within tile
    const int sgrp = threadIdx.x >> 5;   // 0..7 scale group
    const int s0   = sgrp * NS;          // first scale index for this warp
    const int tloc = lane * NT;          // local t offset (multiple of 8)

    // Envelope-truncated k-range (warp-uniform). env(|t|=7) ~ 2e-11.
    const float scale_max = (float)(s0 + NS);
    int r  = (int)(7.0f * scale_max) + 1;
    int k0 = HALF - r;     if (k0 < 0)  k0 = 0;   k0 &= ~3;
    int k1 = HALF + r + 1; if (k1 > FL) k1 = FL;  k1 = (k1 + 3) & ~3;
    if (k1 > FL) k1 = FL;

    // Packed accumulators: (re, im) per (scale, t).
    unsigned long long acc[NS][NT];
#pragma unroll
    for (int si = 0; si < NS; si++)
#pragma unroll
        for (int tt = 0; tt < NT; tt++) acc[si][tt] = 0ull;

    const float TWO_PI_OSC = 37.69911184307752f;  // 2*pi*6

    for (int half = 0; half < 2; half++) {
        const int kbase = half * KHALF;

        __syncthreads();  // drain previous phase before overwriting table
#pragma unroll 4
        for (int j = 0; j < 16; j++) {
            int ci = threadIdx.x * 16 + j;
            int kl = ci >> 5;
            int s  = ci & 31;
            float scale = (float)(s + 1);
            float t   = ((float)(kbase + kl) - 128.0f) / scale;
            float env = expf(-0.5f * t * t);
            float ph  = TWO_PI_OSC * t / scale;
            float sn, cs;
            sincosf(ph, &sn, &cs);
            s_wav[kl][s] = make_float2(env * cs, env * sn);  // (re, im) packed
        }
        __syncthreads();

        int ka = (k0 > kbase) ? k0 : kbase;
        int kb = (k1 < kbase + KHALF) ? k1 : (kbase + KHALF);

        for (int kk = ka; kk < kb; kk += 4) {
            // Signal window for k = kk..kk+3, t = tloc..tloc+7 : 11 floats,
            // broadcast into both halves of a 64b register.
            unsigned long long sp[11];
#pragma unroll
            for (int j = 0; j < 11; j++) sp[j] = pack_dup(s_sig[tloc + kk + j]);

#pragma unroll
            for (int dk = 0; dk < 4; dk++) {
                const int kl = kk + dk - kbase;
                // Packed (re,im) multipliers: float2 in smem IS the packed
                // layout -> single 64-bit LDS each, warp-uniform broadcast.
                unsigned long long wq[NS];
#pragma unroll
                for (int si = 0; si < NS; si++)
                    wq[si] = *(const unsigned long long*)&s_wav[kl][s0 + si];

#pragma unroll
                for (int si = 0; si < NS; si++)
#pragma unroll
                    for (int tt = 0; tt < NT; tt++)
                        acc[si][tt] = ffma2(wq[si], sp[dk + tt], acc[si][tt]);
            }
        }
    }

    // Store. Complex output position c = ((b*NSC + s)*SIG_LEN + t).
    // mode 1: outf[2c] = re, outf[2c+1] = im.   mode 0: outf[c] = re.
    const int tglob = tile0 + tloc;
#pragma unroll
    for (int si = 0; si < NS; si++) {
        long long cbase = ((long long)(b * NSC + s0 + si)) * SIG_LEN + tglob;
#pragma unroll
        for (int tt = 0; tt < NT; tt++) {
            long long c = cbase + tt;
            float re = __uint_as_float((unsigned)(acc[si][tt] & 0xffffffffull));
            float im = __uint_as_float((unsigned)(acc[si][tt] >> 32));
            if (mode) {
                long long f = 2 * c;
                if (f + 1 < w_floats) {
                    outf[f]     = re;
                    outf[f + 1] = im;
                }
            } else {
                if (c < w_floats) outf[c] = re;
            }
        }
    }
}

// ---------------------------------------------------------------------------
// Launch contract. Output treated as out_size FLOATS -> no overrun possible.
// ---------------------------------------------------------------------------
extern "C" void kernel_launch(void* const* d_in, const int* in_sizes, int n_in,
                              void* d_out, int out_size) {
    const void* sig = d_in[0];
    float* outf = (float*)d_out;

    long long n_sig = (long long)in_sizes[0];
    long long structural_sig = (long long)BATCH * SIG_LEN;
    if (structural_sig < n_sig) n_sig = structural_sig;

    long long w_floats = (long long)out_size;          // conservative: 4B/elem
    long long need_interleaved = 2LL * BATCH * NSC * SIG_LEN;  // 67,108,864
    int mode = (w_floats >= need_interleaved) ? 1 : 0;

    dtype_probe_kernel<<<1, 256>>>(sig);

    dim3 grid(SIG_LEN / TILE_T, BATCH);
    morlet_kernel<<<grid, BLOCK_THREADS>>>(sig, outf, n_sig, w_floats, mode);
}

// round 8
// speedup vs baseline: 1.3181x; 1.0965x over previous
#include <cuda_runtime.h>
#include <cuda_bf16.h>
#include <math.h>

// Problem constants
#define FL        256      // filter length
#define NSC       32       // number of scales
#define SIG_LEN   65536
#define BATCH     16
#define HALF      128      // FL/2

// Tiling
#define TILE_T    256      // output positions per block
#define NT        8        // t per thread (contiguous)
#define NS        4        // scales per thread (contiguous)
#define BLOCK_THREADS 256  // 32 t-groups (lanes) x 8 scale-groups (warps)
#define KHALF     128      // coef table covers half the filter at a time

// Input dtype flag decided by probe kernel: 0 = bf16, 1 = float32.
__device__ int g_dtype_flag;

// ---------------------------------------------------------------------------
// Probe (parallel): decide input dtype by reading the FIRST 4KB only.
// ---------------------------------------------------------------------------
__global__ void dtype_probe_kernel(const void* sig) {
    __shared__ int s_crazy;
    if (threadIdx.x == 0) s_crazy = 0;
    __syncthreads();
    const __nv_bfloat16* p = (const __nv_bfloat16*)sig;
    int crazy = 0;
#pragma unroll
    for (int j = 0; j < 8; j++) {
        float v = __bfloat162float(p[threadIdx.x * 8 + j]);
        float a = fabsf(v);
        if (v != v) crazy++;
        else if (a != 0.0f && (a > 64.0f || a < 9.5367431640625e-7f)) crazy++;
    }
    for (int off = 16; off > 0; off >>= 1)
        crazy += __shfl_down_sync(0xffffffffu, crazy, off);
    if ((threadIdx.x & 31) == 0) atomicAdd(&s_crazy, crazy);
    __syncthreads();
    if (threadIdx.x == 0) g_dtype_flag = (s_crazy > 200) ? 1 : 0;
}

// ---------------------------------------------------------------------------
// Packed f32x2 helpers: low word = real, high word = imag.
// ---------------------------------------------------------------------------
__device__ __forceinline__ unsigned long long pack_dup(float x) {
    unsigned long long r;
    asm("mov.b64 %0, {%1, %1};" : "=l"(r) : "r"(__float_as_uint(x)));
    return r;
}
__device__ __forceinline__ unsigned long long ffma2(unsigned long long a,
                                                    unsigned long long b,
                                                    unsigned long long c) {
    unsigned long long d;
    asm("fma.rn.f32x2 %0, %1, %2, %3;" : "=l"(d) : "l"(a), "l"(b), "l"(c));
    return d;
}

// ---------------------------------------------------------------------------
// Fused kernel: in-smem Morlet coef table (two k-halves) + tiled direct
// convolution, packed f32x2 accumulation, LDS.128 for both signal (aligned
// float4) and coefficients (warp-uniform broadcast ulonglong2).
// ---------------------------------------------------------------------------
__global__ void __launch_bounds__(BLOCK_THREADS)
morlet_kernel(const void* __restrict__ sig_raw, float* __restrict__ outf,
              long long n_sig, long long w_floats, int mode) {
    __shared__ __align__(16) float  s_sig[TILE_T + FL];  // 2 KB signal window
    __shared__ __align__(16) float2 s_wav[KHALF][NSC];   // 32 KB coef table

    const int b     = blockIdx.y;
    const int tile0 = blockIdx.x * TILE_T;
    const long long sbase = (long long)b * SIG_LEN;
    const int dtype = g_dtype_flag;           // uniform across grid

    const float*          sigf = (const float*)sig_raw;
    const __nv_bfloat16*  sigb = (const __nv_bfloat16*)sig_raw;

    // Cooperative, fully-guarded staging of the signal window (zero-padded).
    for (int i = threadIdx.x; i < TILE_T + FL; i += BLOCK_THREADS) {
        int gl = tile0 - HALF + i;
        long long g = sbase + gl;
        float v = 0.0f;
        if (gl >= 0 && gl < SIG_LEN && g >= 0 && g < n_sig) {
            v = dtype ? sigf[g] : __bfloat162float(sigb[g]);
        }
        s_sig[i] = v;
    }

    const int lane = threadIdx.x & 31;   // t-group within tile
    const int sgrp = threadIdx.x >> 5;   // 0..7 scale group
    const int s0   = sgrp * NS;          // first scale index (even -> 16B align)
    const int tloc = lane * NT;          // local t offset (multiple of 8)

    // Envelope-truncated k-range (warp-uniform). env(|t|=7) ~ 2e-11.
    const float scale_max = (float)(s0 + NS);
    int r  = (int)(7.0f * scale_max) + 1;
    int k0 = HALF - r;     if (k0 < 0)  k0 = 0;   k0 &= ~3;
    int k1 = HALF + r + 1; if (k1 > FL) k1 = FL;  k1 = (k1 + 3) & ~3;
    if (k1 > FL) k1 = FL;

    // Packed accumulators: (re, im) per (scale, t).
    unsigned long long acc[NS][NT];
#pragma unroll
    for (int si = 0; si < NS; si++)
#pragma unroll
        for (int tt = 0; tt < NT; tt++) acc[si][tt] = 0ull;

    const float TWO_PI_OSC = 37.69911184307752f;  // 2*pi*6

    for (int half = 0; half < 2; half++) {
        const int kbase = half * KHALF;

        __syncthreads();  // drain previous phase before overwriting table
#pragma unroll 4
        for (int j = 0; j < 16; j++) {
            int ci = threadIdx.x * 16 + j;
            int kl = ci >> 5;
            int s  = ci & 31;
            float scale = (float)(s + 1);
            float t   = ((float)(kbase + kl) - 128.0f) / scale;
            float env = expf(-0.5f * t * t);
            float ph  = TWO_PI_OSC * t / scale;
            float sn, cs;
            sincosf(ph, &sn, &cs);
            s_wav[kl][s] = make_float2(env * cs, env * sn);  // (re, im) packed
        }
        __syncthreads();

        int ka = (k0 > kbase) ? k0 : kbase;
        int kb = (k1 < kbase + KHALF) ? k1 : (kbase + KHALF);

        for (int kk = ka; kk < kb; kk += 4) {
            // Signal window for k = kk..kk+3, t = tloc..tloc+7 : 11 floats.
            // tloc, kk multiples of 4 -> 16B-aligned LDS.128 x3.
            float4 a0 = *(const float4*)&s_sig[tloc + kk];
            float4 a1 = *(const float4*)&s_sig[tloc + kk + 4];
            float4 a2 = *(const float4*)&s_sig[tloc + kk + 8];
            unsigned long long sp[11];
            sp[0]  = pack_dup(a0.x);  sp[1]  = pack_dup(a0.y);
            sp[2]  = pack_dup(a0.z);  sp[3]  = pack_dup(a0.w);
            sp[4]  = pack_dup(a1.x);  sp[5]  = pack_dup(a1.y);
            sp[6]  = pack_dup(a1.z);  sp[7]  = pack_dup(a1.w);
            sp[8]  = pack_dup(a2.x);  sp[9]  = pack_dup(a2.y);
            sp[10] = pack_dup(a2.z);

#pragma unroll
            for (int dk = 0; dk < 4; dk++) {
                const int kl = kk + dk - kbase;
                // 4 packed (re,im) multipliers = 32B contiguous:
                // two warp-uniform LDS.128, halves already packed as u64.
                ulonglong2 q01 = *(const ulonglong2*)&s_wav[kl][s0];
                ulonglong2 q23 = *(const ulonglong2*)&s_wav[kl][s0 + 2];
                unsigned long long wq[NS];
                wq[0] = q01.x; wq[1] = q01.y;
                wq[2] = q23.x; wq[3] = q23.y;

#pragma unroll
                for (int si = 0; si < NS; si++)
#pragma unroll
                    for (int tt = 0; tt < NT; tt++)
                        acc[si][tt] = ffma2(wq[si], sp[dk + tt], acc[si][tt]);
            }
        }
    }

    // Store. Complex output position c = ((b*NSC + s)*SIG_LEN + t).
    // mode 1: outf[2c]=re, outf[2c+1]=im.  mode 0: outf[c]=re.
    const int tglob = tile0 + tloc;
#pragma unroll
    for (int si = 0; si < NS; si++) {
        long long cbase = ((long long)(b * NSC + s0 + si)) * SIG_LEN + tglob;
#pragma unroll
        for (int tt = 0; tt < NT; tt++) {
            long long c = cbase + tt;
            float re = __uint_as_float((unsigned)(acc[si][tt] & 0xffffffffull));
            float im = __uint_as_float((unsigned)(acc[si][tt] >> 32));
            if (mode) {
                long long f = 2 * c;
                if (f + 1 < w_floats) {
                    outf[f]     = re;
                    outf[f + 1] = im;
                }
            } else {
                if (c < w_floats) outf[c] = re;
            }
        }
    }
}

// ---------------------------------------------------------------------------
// Launch contract. Output treated as out_size FLOATS -> no overrun possible.
// ---------------------------------------------------------------------------
extern "C" void kernel_launch(void* const* d_in, const int* in_sizes, int n_in,
                              void* d_out, int out_size) {
    const void* sig = d_in[0];
    float* outf = (float*)d_out;

    long long n_sig = (long long)in_sizes[0];
    long long structural_sig = (long long)BATCH * SIG_LEN;
    if (structural_sig < n_sig) n_sig = structural_sig;

    long long w_floats = (long long)out_size;          // conservative: 4B/elem
    long long need_interleaved = 2LL * BATCH * NSC * SIG_LEN;  // 67,108,864
    int mode = (w_floats >= need_interleaved) ? 1 : 0;

    dtype_probe_kernel<<<1, 256>>>(sig);

    dim3 grid(SIG_LEN / TILE_T, BATCH);
    morlet_kernel<<<grid, BLOCK_THREADS>>>(sig, outf, n_sig, w_floats, mode);
}

// round 9
// speedup vs baseline: 1.7495x; 1.3273x over previous
#include <cuda_runtime.h>
#include <cuda_bf16.h>
#include <math.h>

// Problem constants
#define FL        256      // filter length
#define NSC       32       // number of scales
#define SIG_LEN   65536
#define BATCH     16
#define HALF      128      // FL/2

// Tiling: block = (2048-t tile, batch, scale-group-of-4)
#define TILE_T    2048     // output positions per block
#define NT        8        // t per thread (contiguous)
#define NS        4        // scales per thread (whole block shares them)
#define BLOCK_THREADS 256  // 8 warps x 32 lanes; warp w covers t [w*256,(w+1)*256)

// Input dtype flag decided by probe kernel: 0 = bf16, 1 = float32.
__device__ int g_dtype_flag;

// ---------------------------------------------------------------------------
// Probe (parallel): decide input dtype by reading the FIRST 4KB only.
// ---------------------------------------------------------------------------
__global__ void dtype_probe_kernel(const void* sig) {
    __shared__ int s_crazy;
    if (threadIdx.x == 0) s_crazy = 0;
    __syncthreads();
    const __nv_bfloat16* p = (const __nv_bfloat16*)sig;
    int crazy = 0;
#pragma unroll
    for (int j = 0; j < 8; j++) {
        float v = __bfloat162float(p[threadIdx.x * 8 + j]);
        float a = fabsf(v);
        if (v != v) crazy++;
        else if (a != 0.0f && (a > 64.0f || a < 9.5367431640625e-7f)) crazy++;
    }
    for (int off = 16; off > 0; off >>= 1)
        crazy += __shfl_down_sync(0xffffffffu, crazy, off);
    if ((threadIdx.x & 31) == 0) atomicAdd(&s_crazy, crazy);
    __syncthreads();
    if (threadIdx.x == 0) g_dtype_flag = (s_crazy > 200) ? 1 : 0;
}

// ---------------------------------------------------------------------------
// Packed f32x2 helpers: low word = real, high word = imag.
// ---------------------------------------------------------------------------
__device__ __forceinline__ unsigned long long pack_dup(float x) {
    unsigned long long r;
    asm("mov.b64 %0, {%1, %1};" : "=l"(r) : "r"(__float_as_uint(x)));
    return r;
}
__device__ __forceinline__ unsigned long long ffma2(unsigned long long a,
                                                    unsigned long long b,
                                                    unsigned long long c) {
    unsigned long long d;
    asm("fma.rn.f32x2 %0, %1, %2, %3;" : "=l"(d) : "l"(a), "l"(b), "l"(c));
    return d;
}

// ---------------------------------------------------------------------------
// Balanced kernel: one scale-group (4 scales) per block; all warps do
// identical envelope-truncated work. Coef table built once (8 KB).
// ---------------------------------------------------------------------------
__global__ void __launch_bounds__(BLOCK_THREADS)
morlet_kernel(const void* __restrict__ sig_raw, float* __restrict__ outf,
              long long n_sig, long long w_floats, int mode) {
    __shared__ __align__(16) float  s_sig[TILE_T + FL];  // 9 KB signal window
    __shared__ __align__(16) float2 s_wav[FL][NS];       // 8 KB coef table

    const int b     = blockIdx.y;
    const int tile0 = blockIdx.x * TILE_T;
    const int grp   = blockIdx.z;        // scale group 0..7
    const int s0    = grp * NS;          // first scale index of this block
    const long long sbase = (long long)b * SIG_LEN;
    const int dtype = g_dtype_flag;      // uniform across grid

    const float*          sigf = (const float*)sig_raw;
    const __nv_bfloat16*  sigb = (const __nv_bfloat16*)sig_raw;

    // Stage signal window (zero-padded, fully guarded): 2304 floats.
    for (int i = threadIdx.x; i < TILE_T + FL; i += BLOCK_THREADS) {
        int gl = tile0 - HALF + i;
        long long g = sbase + gl;
        float v = 0.0f;
        if (gl >= 0 && gl < SIG_LEN && g >= 0 && g < n_sig) {
            v = dtype ? sigf[g] : __bfloat162float(sigb[g]);
        }
        s_sig[i] = v;
    }

    // Build coef table for this group's 4 scales, all 256 k: 1024 coefs.
    const float TWO_PI_OSC = 37.69911184307752f;  // 2*pi*6
#pragma unroll
    for (int j = 0; j < 4; j++) {
        int ci = threadIdx.x * 4 + j;    // 0..1023
        int kl = ci >> 2;                // k 0..255
        int si = ci & 3;                 // scale within group
        float scale = (float)(s0 + si + 1);
        float t   = ((float)kl - 128.0f) / scale;
        float env = expf(-0.5f * t * t);
        float ph  = TWO_PI_OSC * t / scale;
        float sn, cs;
        sincosf(ph, &sn, &cs);
        s_wav[kl][si] = make_float2(env * cs, env * sn);
    }
    __syncthreads();

    const int lane = threadIdx.x & 31;
    const int wrp  = threadIdx.x >> 5;            // 0..7
    const int tloc = wrp * 256 + lane * NT;       // multiple of 8

    // Envelope-truncated k-range (same for whole block). env(|t|=7)~2e-11.
    const float scale_max = (float)(s0 + NS);
    int r  = (int)(7.0f * scale_max) + 1;
    int k0 = HALF - r;     if (k0 < 0)  k0 = 0;   k0 &= ~3;
    int k1 = HALF + r + 1; if (k1 > FL) k1 = FL;  k1 = (k1 + 3) & ~3;
    if (k1 > FL) k1 = FL;

    // Packed accumulators: (re, im) per (scale, t).
    unsigned long long acc[NS][NT];
#pragma unroll
    for (int si = 0; si < NS; si++)
#pragma unroll
        for (int tt = 0; tt < NT; tt++) acc[si][tt] = 0ull;

    for (int kk = k0; kk < k1; kk += 4) {
        // Signal: 11 floats via 3 aligned LDS.128, broadcast to f32x2.
        float4 a0 = *(const float4*)&s_sig[tloc + kk];
        float4 a1 = *(const float4*)&s_sig[tloc + kk + 4];
        float4 a2 = *(const float4*)&s_sig[tloc + kk + 8];
        unsigned long long sp[11];
        sp[0]  = pack_dup(a0.x);  sp[1]  = pack_dup(a0.y);
        sp[2]  = pack_dup(a0.z);  sp[3]  = pack_dup(a0.w);
        sp[4]  = pack_dup(a1.x);  sp[5]  = pack_dup(a1.y);
        sp[6]  = pack_dup(a1.z);  sp[7]  = pack_dup(a1.w);
        sp[8]  = pack_dup(a2.x);  sp[9]  = pack_dup(a2.y);
        sp[10] = pack_dup(a2.z);

#pragma unroll
        for (int dk = 0; dk < 4; dk++) {
            const int kl = kk + dk;
            // 4 packed (re,im) multipliers = one 32B row: 2 broadcast LDS.128.
            ulonglong2 q01 = *(const ulonglong2*)&s_wav[kl][0];
            ulonglong2 q23 = *(const ulonglong2*)&s_wav[kl][2];
            unsigned long long wq[NS];
            wq[0] = q01.x; wq[1] = q01.y;
            wq[2] = q23.x; wq[3] = q23.y;

#pragma unroll
            for (int si = 0; si < NS; si++)
#pragma unroll
                for (int tt = 0; tt < NT; tt++)
                    acc[si][tt] = ffma2(wq[si], sp[dk + tt], acc[si][tt]);
        }
    }

    // Store. Complex output position c = ((b*NSC + s)*SIG_LEN + t).
    const int tglob = tile0 + tloc;
#pragma unroll
    for (int si = 0; si < NS; si++) {
        long long cbase = ((long long)(b * NSC + s0 + si)) * SIG_LEN + tglob;
#pragma unroll
        for (int tt = 0; tt < NT; tt++) {
            long long c = cbase + tt;
            float re = __uint_as_float((unsigned)(acc[si][tt] & 0xffffffffull));
            float im = __uint_as_float((unsigned)(acc[si][tt] >> 32));
            if (mode) {
                long long f = 2 * c;
                if (f + 1 < w_floats) {
                    outf[f]     = re;
                    outf[f + 1] = im;
                }
            } else {
                if (c < w_floats) outf[c] = re;
            }
        }
    }
}

// ---------------------------------------------------------------------------
// Launch contract. Output treated as out_size FLOATS -> no overrun possible.
// ---------------------------------------------------------------------------
extern "C" void kernel_launch(void* const* d_in, const int* in_sizes, int n_in,
                              void* d_out, int out_size) {
    const void* sig = d_in[0];
    float* outf = (float*)d_out;

    long long n_sig = (long long)in_sizes[0];
    long long structural_sig = (long long)BATCH * SIG_LEN;
    if (structural_sig < n_sig) n_sig = structural_sig;

    long long w_floats = (long long)out_size;          // conservative: 4B/elem
    long long need_interleaved = 2LL * BATCH * NSC * SIG_LEN;  // 67,108,864
    int mode = (w_floats >= need_interleaved) ? 1 : 0;

    dtype_probe_kernel<<<1, 256>>>(sig);

    dim3 grid(SIG_LEN / TILE_T, BATCH, NSC / NS);      // (32, 16, 8)
    morlet_kernel<<<grid, BLOCK_THREADS>>>(sig, outf, n_sig, w_floats, mode);
}